// round 10
// baseline (speedup 1.0000x reference)
#include <cuda_runtime.h>
#include <cuda_bf16.h>
#include <cuda_fp16.h>
#include <cstdint>

// ScaledDotProductAttention B=1 H=8 S=2048 D=64, sm_103 base ISA.
// Single-pass p: CTA = 32 q-rows, e-tile kept in smem (f16) across the full
// kv sweep; p written ONCE normalized (no unnormalized write + re-read).
// QK: bf16 hi/lo 3-combo MMA. PV: e(f16) x V(f16), 1 combo.
// d_out = [out 1x8x2048x64 | p_attn 1x8x2048x2048].

#define SQ 2048
#define HD 64
#define NH 8
#define MT 32           // q rows per CTA
#define CH 64           // kv per chunk
#define NCH (SQ / CH)   // 32
#define THREADS 256

// ---- smem layout (bytes) ----
#define S_EH   0                      // e f16 [32][2048], row stride 4096 (128KB)
#define EH_ROW 4096
#define S_ST0  131072                 // 3 stages of 32KB
#define STG    32768
// within a stage: khi 0 | klo 8192 | vh 16384 | sph 24576
#define S_TOTAL (S_ST0 + 3 * STG)     // 229376
// epilogue overlays (stage area, used after the loop)
#define S_LPART S_ST0                 // f32 [8][32]  = 1KB
#define S_OSM   (S_ST0 + 1024)        // f32 [4][32][64] = 32KB
#define S_LF    (S_ST0 + 1024 + 32768)// f32 [32]

__device__ __nv_bfloat16 g_khi[NH * SQ * HD];
__device__ __nv_bfloat16 g_klo[NH * SQ * HD];
__device__ __half        g_vh [NH * SQ * HD];

__device__ __forceinline__ uint32_t smem_u32(const void* p) {
    uint32_t a;
    asm("{ .reg .u64 t; cvta.to.shared.u64 t, %1; cvt.u32.u64 %0, t; }"
        : "=r"(a) : "l"(p));
    return a;
}
__device__ __forceinline__ void cpa16(uint32_t dst, const void* src) {
    asm volatile("cp.async.cg.shared.global [%0], [%1], 16;"
                 :: "r"(dst), "l"(src));
}
__device__ __forceinline__ void cpa_commit() {
    asm volatile("cp.async.commit_group;" ::: "memory");
}
__device__ __forceinline__ void cpa_wait0() {
    asm volatile("cp.async.wait_group 0;" ::: "memory");
}
__device__ __forceinline__ void cpa_wait1() {
    asm volatile("cp.async.wait_group 1;" ::: "memory");
}
__device__ __forceinline__ void ldsm4(uint32_t* r, uint32_t addr) {
    asm volatile("ldmatrix.sync.aligned.m8n8.x4.shared.b16 {%0,%1,%2,%3}, [%4];"
                 : "=r"(r[0]), "=r"(r[1]), "=r"(r[2]), "=r"(r[3]) : "r"(addr));
}
__device__ __forceinline__ void ldsm4t(uint32_t* r, uint32_t addr) {
    asm volatile("ldmatrix.sync.aligned.m8n8.x4.trans.shared.b16 {%0,%1,%2,%3}, [%4];"
                 : "=r"(r[0]), "=r"(r[1]), "=r"(r[2]), "=r"(r[3]) : "r"(addr));
}
__device__ __forceinline__ void mma_bf16(float* c, const uint32_t* a,
                                         uint32_t b0, uint32_t b1) {
    asm volatile(
        "mma.sync.aligned.m16n8k16.row.col.f32.bf16.bf16.f32 "
        "{%0,%1,%2,%3}, {%4,%5,%6,%7}, {%8,%9}, {%0,%1,%2,%3};"
        : "+f"(c[0]), "+f"(c[1]), "+f"(c[2]), "+f"(c[3])
        : "r"(a[0]), "r"(a[1]), "r"(a[2]), "r"(a[3]), "r"(b0), "r"(b1));
}
__device__ __forceinline__ void mma_f16(float* c, const uint32_t* a,
                                        uint32_t b0, uint32_t b1) {
    asm volatile(
        "mma.sync.aligned.m16n8k16.row.col.f32.f16.f16.f32 "
        "{%0,%1,%2,%3}, {%4,%5,%6,%7}, {%8,%9}, {%0,%1,%2,%3};"
        : "+f"(c[0]), "+f"(c[1]), "+f"(c[2]), "+f"(c[3])
        : "r"(a[0]), "r"(a[1]), "r"(a[2]), "r"(a[3]), "r"(b0), "r"(b1));
}
__device__ __forceinline__ uint32_t bf2u(__nv_bfloat162 x) {
    uint32_t r; *(__nv_bfloat162*)&r = x; return r;
}
__device__ __forceinline__ void split_pack2(float a, float b,
                                            uint32_t& hi, uint32_t& lo) {
    __nv_bfloat162 h = __floats2bfloat162_rn(a, b);
    hi = bf2u(h);
    lo = bf2u(__floats2bfloat162_rn(a - __bfloat162float(h.x),
                                    b - __bfloat162float(h.y)));
}
// 128B-row tiles (K/V/Q staging): SW128-style swizzle
__device__ __forceinline__ uint32_t swz(int row, int colB) {
    return (uint32_t)(((row << 7) + colB) ^ ((row & 7) << 4));
}
// e-buffer: row stride 4096B, XOR on 16B units
__device__ __forceinline__ uint32_t eoff(int row, int u16) {
    return (uint32_t)(row * EH_ROW + ((u16 ^ ((row & 7) << 1)) << 4));
}
// sph stage: [32 rows][64 f32], 256B rows, XOR on 16B units
__device__ __forceinline__ uint32_t soff(int row, int u16) {
    return (uint32_t)((row << 8) + ((u16 ^ ((row & 7) << 1)) << 4));
}

// ---------------- prep: K -> bf16 hi/lo, V -> f16 ----------------
__global__ __launch_bounds__(256)
void conv_kv(const float* __restrict__ k, const float* __restrict__ v)
{
    int idx = blockIdx.x * 256 + threadIdx.x;   // over NH*SQ*HD/4
    float4 kf = ((const float4*)k)[idx];
    uint32_t h0, l0, h1, l1;
    split_pack2(kf.x, kf.y, h0, l0);
    split_pack2(kf.z, kf.w, h1, l1);
    ((uint2*)g_khi)[idx] = make_uint2(h0, h1);
    ((uint2*)g_klo)[idx] = make_uint2(l0, l1);
    float4 vf = ((const float4*)v)[idx];
    __half2 v0 = __float22half2_rn(make_float2(vf.x, vf.y));
    __half2 v1 = __float22half2_rn(make_float2(vf.z, vf.w));
    ((uint2*)g_vh)[idx] = make_uint2(*(uint32_t*)&v0, *(uint32_t*)&v1);
}

// ---------------- main fused attention, single-pass p ----------------
__global__ __launch_bounds__(THREADS)
void attn_mma(const float* __restrict__ q, const float* __restrict__ sph,
              const int* __restrict__ mask,
              float* __restrict__ out, float* __restrict__ p)
{
    extern __shared__ char smem[];
    const uint32_t sb = smem_u32(smem);

    const int t = threadIdx.x, w = t >> 5, lane = t & 31;
    const int g = lane >> 2, lam = lane & 3;
    const int kt = w & 3;              // PV k-tile (16 kv)
    const int dh = w >> 2;             // PV dim-half (32 dims)
    const int h = blockIdx.y, q0 = blockIdx.x * MT;

    const float* qh  = q + ((size_t)h * SQ + q0) * HD;
    const float* sc0 = sph + ((size_t)h * SQ + q0) * SQ;
    const int*   mc0 = mask + ((size_t)h * SQ + q0) * SQ;
    float*       pc0 = p + ((size_t)h * SQ + q0) * SQ;

    // ---- prologue: stage Q (x1/8) hi/lo in EH area, load a-frags ----
    #pragma unroll
    for (int i = 0; i < 2; ++i) {                // 512 float4 = 32x64
        int idx = t + THREADS * i;
        int row = idx >> 4, gq = idx & 15;
        float4 f = ((const float4*)qh)[idx];
        f.x *= 0.125f; f.y *= 0.125f; f.z *= 0.125f; f.w *= 0.125f;
        uint32_t h0, l0, h1, l1;
        split_pack2(f.x, f.y, h0, l0);
        split_pack2(f.z, f.w, h1, l1);
        uint32_t off = swz(row, gq * 8);
        *(uint2*)(smem + S_EH + off)        = make_uint2(h0, h1);
        *(uint2*)(smem + S_EH + 4096 + off) = make_uint2(l0, l1);
    }
    __syncthreads();
    uint32_t ah[2][4][4], al[2][4][4];
    {
        int arow = ((lane >> 3) & 1) * 8 + (lane & 7);
        int acol = ((lane >> 4) & 1) * 16;
        #pragma unroll
        for (int rt = 0; rt < 2; ++rt)
            #pragma unroll
            for (int kk = 0; kk < 4; ++kk) {
                uint32_t aoff = swz(rt * 16 + arow, acol + kk * 32);
                ldsm4(ah[rt][kk], sb + S_EH + aoff);
                ldsm4(al[rt][kk], sb + S_EH + 4096 + aoff);
            }
    }
    // loop's first top-barrier orders these reads vs first e-writes.

    const __nv_bfloat16* kh = g_khi + (size_t)h * SQ * HD;
    const __nv_bfloat16* kl = g_klo + (size_t)h * SQ * HD;
    const __half*        vh = g_vh  + (size_t)h * SQ * HD;

    auto prefetch = [&](int cc, int st) {
        const uint32_t base = sb + S_ST0 + (uint32_t)st * STG;
        #pragma unroll
        for (int it = 0; it < 6; ++it) {       // 1536 16B units: khi|klo|vh
            int idx = t + THREADS * it;
            int arr = idx >> 9;
            int rem = idx & 511, row = rem >> 3, u = rem & 7;
            const void* src = (arr == 0) ? (const void*)(kh + (size_t)(cc + row) * HD + u * 8)
                            : (arr == 1) ? (const void*)(kl + (size_t)(cc + row) * HD + u * 8)
                                         : (const void*)(vh + (size_t)(cc + row) * HD + u * 8);
            cpa16(base + arr * 8192 + swz(row, u * 16), src);
        }
        #pragma unroll
        for (int it = 0; it < 2; ++it) {       // sph: 512 units = 32 rows x 16
            int idx = t + THREADS * it;
            int row = idx >> 4, u16 = idx & 15;
            cpa16(base + 24576 + soff(row, u16),
                  sc0 + (size_t)row * SQ + cc + u16 * 4);
        }
        cpa_commit();
    };

    prefetch(0, 0);
    prefetch(CH, 1);

    float O[2][4][4];
    #pragma unroll
    for (int a = 0; a < 2; ++a)
        #pragma unroll
        for (int b = 0; b < 4; ++b)
            #pragma unroll
            for (int c = 0; c < 4; ++c) O[a][b][c] = 0.f;
    float lacc[2][2] = {{0.f, 0.f}, {0.f, 0.f}};

    int st = 0;
    for (int ch = 0; ch < NCH; ++ch, st = (st == 2 ? 0 : st + 1)) {
        const int c0 = ch * CH;

        // mask direct loads (hidden under QK)
        int2 mk[2][2];
        #pragma unroll
        for (int rt = 0; rt < 2; ++rt)
            #pragma unroll
            for (int hf = 0; hf < 2; ++hf)
                mk[rt][hf] = __ldcs((const int2*)(mc0 +
                    (size_t)(rt * 16 + hf * 8 + g) * SQ + c0 + w * 8 + lam * 2));

        if (ch + 2 < NCH) cpa_wait1(); else cpa_wait0();
        __syncthreads();
        if (ch + 2 < NCH) {
            int st2 = st + 2; if (st2 >= 3) st2 -= 3;
            prefetch(c0 + 2 * CH, st2);
        }

        const int stg = S_ST0 + st * STG;
        const uint32_t kvb = sb + stg;

        // ---- QK^T: warp w owns kv n-tile w (8 cols), both row-tiles -------
        float S[2][4];
        S[0][0] = S[0][1] = S[0][2] = S[0][3] = 0.f;
        S[1][0] = S[1][1] = S[1][2] = S[1][3] = 0.f;
        #pragma unroll
        for (int kk2 = 0; kk2 < 2; ++kk2) {
            uint32_t koff = swz(w * 8 + (lane & 7),
                                kk2 * 64 + (lane >> 3) * 16);
            uint32_t bh[4], bl[4];
            ldsm4(bh, kvb + koff);            // khi
            ldsm4(bl, kvb + 8192 + koff);     // klo
            #pragma unroll
            for (int sub = 0; sub < 2; ++sub) {
                const int ktile = kk2 * 2 + sub;
                #pragma unroll
                for (int rt = 0; rt < 2; ++rt) {
                    mma_bf16(S[rt], ah[rt][ktile], bh[sub * 2], bh[sub * 2 + 1]);
                    mma_bf16(S[rt], ah[rt][ktile], bl[sub * 2], bl[sub * 2 + 1]);
                    mma_bf16(S[rt], al[rt][ktile], bh[sub * 2], bh[sub * 2 + 1]);
                }
            }
        }

        // ---- e = mask * exp(s*sph) -> f16 e-buffer -------------------------
        const int u8 = w * 4 + lam;           // sph float2 unit
        const int eu = (c0 >> 3) + w;         // e-buffer 16B unit
        #pragma unroll
        for (int rt = 0; rt < 2; ++rt) {
            const int row0 = rt * 16 + g, row1 = row0 + 8;
            const char* sphS = smem + stg + 24576;
            uint32_t so = (uint32_t)((u8 ^ (g << 2)) << 3);
            float2 sA = *(const float2*)(sphS + row0 * 256 + so);
            float2 sB = *(const float2*)(sphS + row1 * 256 + so);
            float e0 = mk[rt][0].x ? __expf(S[rt][0] * sA.x) : 0.f;
            float e1 = mk[rt][0].y ? __expf(S[rt][1] * sA.y) : 0.f;
            float e2 = mk[rt][1].x ? __expf(S[rt][2] * sB.x) : 0.f;
            float e3 = mk[rt][1].y ? __expf(S[rt][3] * sB.y) : 0.f;
            lacc[rt][0] += e0 + e1;
            lacc[rt][1] += e2 + e3;
            __half2 p0 = __float22half2_rn(make_float2(e0, e1));
            __half2 p1 = __float22half2_rn(make_float2(e2, e3));
            *(uint32_t*)(smem + S_EH + eoff(row0, eu) + lam * 4) = *(uint32_t*)&p0;
            *(uint32_t*)(smem + S_EH + eoff(row1, eu) + lam * 4) = *(uint32_t*)&p1;
        }
        __syncthreads();   // e tile complete for cross-warp PV reads

        // ---- PV: warp w = (kt, dh): O += E[.,kt] * V[kt, dh] ---------------
        uint32_t ea[2][4];
        {
            const int u0 = (c0 >> 3) + kt * 2;
            #pragma unroll
            for (int rt = 0; rt < 2; ++rt) {
                int rowA = rt * 16 + (lane & 7) + ((lane >> 3) & 1) * 8;
                ldsm4(ea[rt], sb + S_EH + eoff(rowA, u0 + (lane >> 4)));
            }
        }
        #pragma unroll
        for (int ntp2 = 0; ntp2 < 2; ++ntp2) {
            uint32_t voff = swz(kt * 16 + (lane & 15),
                                dh * 64 + (ntp2 * 2 + (lane >> 4)) * 16);
            uint32_t vb[4];
            ldsm4t(vb, kvb + 16384 + voff);
            #pragma unroll
            for (int sub = 0; sub < 2; ++sub) {
                const int nt = ntp2 * 2 + sub;
                #pragma unroll
                for (int rt = 0; rt < 2; ++rt)
                    mma_f16(O[rt][nt], ea[rt], vb[sub * 2], vb[sub * 2 + 1]);
            }
        }
    }

    // ---- epilogue ----------------------------------------------------------
    __syncthreads();   // all PV stage/e reads done; stage area reusable
    float* l_part = (float*)(smem + S_LPART);
    float* osm    = (float*)(smem + S_OSM);
    float* l_f    = (float*)(smem + S_LF);

    #pragma unroll
    for (int rt = 0; rt < 2; ++rt)
        #pragma unroll
        for (int hf = 0; hf < 2; ++hf) {
            float v = lacc[rt][hf];
            v += __shfl_xor_sync(0xffffffffu, v, 1);
            v += __shfl_xor_sync(0xffffffffu, v, 2);
            if (lam == 0) l_part[w * 32 + rt * 16 + hf * 8 + g] = v;
        }
    // O partials -> osm[kt][row][dim]
    #pragma unroll
    for (int rt = 0; rt < 2; ++rt)
        #pragma unroll
        for (int nt = 0; nt < 4; ++nt) {
            const int d = dh * 32 + nt * 8 + lam * 2;
            *(float2*)(osm + (size_t)kt * 2048 + (rt * 16 + g) * 64 + d) =
                make_float2(O[rt][nt][0], O[rt][nt][1]);
            *(float2*)(osm + (size_t)kt * 2048 + (rt * 16 + g + 8) * 64 + d) =
                make_float2(O[rt][nt][2], O[rt][nt][3]);
        }
    __syncthreads();
    if (t < 32) {
        float s = 0.f;
        #pragma unroll
        for (int ww = 0; ww < 8; ++ww) s += l_part[ww * 32 + t];
        l_f[t] = s;
    }
    __syncthreads();

    // out = (sum_kt O) / l
    {
        const int row = t >> 3, d0 = (t & 7) * 8;
        float acc[8];
        #pragma unroll
        for (int i = 0; i < 8; ++i) acc[i] = 0.f;
        #pragma unroll
        for (int kk = 0; kk < 4; ++kk) {
            const float* o = osm + (size_t)kk * 2048 + row * 64 + d0;
            float4 x0 = *(const float4*)o;
            float4 x1 = *(const float4*)(o + 4);
            acc[0] += x0.x; acc[1] += x0.y; acc[2] += x0.z; acc[3] += x0.w;
            acc[4] += x1.x; acc[5] += x1.y; acc[6] += x1.z; acc[7] += x1.w;
        }
        const float inv = 1.0f / l_f[row];
        float* od = out + ((size_t)h * SQ + q0 + row) * HD + d0;
        *(float4*)od       = make_float4(acc[0] * inv, acc[1] * inv, acc[2] * inv, acc[3] * inv);
        *(float4*)(od + 4) = make_float4(acc[4] * inv, acc[5] * inv, acc[6] * inv, acc[7] * inv);
    }

    // p = e / l, single normalized write from the smem e-buffer
    {
        const int row = t >> 3, lane8 = t & 7;
        const float inv = 1.0f / l_f[row];
        float* prow = pc0 + (size_t)row * SQ;
        #pragma unroll 4
        for (int it = 0; it < 64; ++it) {
            const int c4 = lane8 + 8 * it;            // float4 index 0..511
            uint32_t off = eoff(row, c4 >> 1) + (c4 & 1) * 8;
            uint2 hh = *(const uint2*)(smem + S_EH + off);
            float2 f0 = __half22float2(*(const __half2*)&hh.x);
            float2 f1 = __half22float2(*(const __half2*)&hh.y);
            __stcs((float4*)(prow + c4 * 4),
                   make_float4(f0.x * inv, f0.y * inv, f1.x * inv, f1.y * inv));
        }
    }
}

extern "C" void kernel_launch(void* const* d_in, const int* in_sizes, int n_in,
                              void* d_out, int out_size)
{
    const float* q    = (const float*)d_in[0];
    const float* k    = (const float*)d_in[1];
    const float* v    = (const float*)d_in[2];
    const float* sph  = (const float*)d_in[3];
    const int*   mask = (const int*)d_in[4];

    float* out = (float*)d_out;                 // [1,8,2048,64]
    float* p   = out + (size_t)NH * SQ * HD;    // [1,8,2048,2048]

    cudaFuncSetAttribute(attn_mma, cudaFuncAttributeMaxDynamicSharedMemorySize,
                         S_TOTAL);

    conv_kv<<<NH * SQ * HD / 4 / 256, 256>>>(k, v);
    dim3 grid(SQ / MT, NH);
    attn_mma<<<grid, THREADS, S_TOTAL>>>(q, sph, mask, out, p);
}

// round 11
// speedup vs baseline: 1.4046x; 1.4046x over previous
#include <cuda_runtime.h>
#include <cuda_bf16.h>
#include <cuda_fp16.h>
#include <cstdint>

// ScaledDotProductAttention B=1 H=8 S=2048 D=64, sm_103 base ISA.
// mma.sync m16n8k16 bf16 (split hi/lo, ~1e-5 on out), 3-stage cp.async
// pipeline (CH=32), 512 threads/CTA: warp = (row-tile rt, kv-half nh).
// Unnormalized e goes to a f16 gmem scratch (halves intermediate traffic);
// fused epilogue reads it back (L2-hot) and writes p ONCE, normalized fp32.
// d_out = [out 1x8x2048x64 | p_attn 1x8x2048x2048].

#define SQ 2048
#define HD 64
#define NH 8
#define MT 128          // q rows per CTA
#define CH 32           // kv per chunk
#define NCH (SQ / CH)   // 64
#define THREADS 512

// ---- smem layout (bytes): 3 stages of 48KB ----
// stage s at s*STG: khi 0 | klo 4096 | vhi 8192 | vlo 12288 | sph 16384 | msk 32768
#define STG   49152
#define S_QHI 0                          // prologue only (overlays stage 0)
#define S_QLO 16384
#define S_OSM 0                          // epilogue O reduction (32KB, overlays)
#define S_LSM 32768                      // f32 [2][128] row-sum halves
#define S_TOTAL (3 * STG)                // 147456

__device__ __nv_bfloat16 g_khi[NH * SQ * HD];
__device__ __nv_bfloat16 g_klo[NH * SQ * HD];
__device__ __nv_bfloat16 g_vhi[NH * SQ * HD];
__device__ __nv_bfloat16 g_vlo[NH * SQ * HD];
__device__ __half        g_e[(size_t)NH * SQ * SQ];   // unnormalized exp scratch

__device__ __forceinline__ uint32_t smem_u32(const void* p) {
    uint32_t a;
    asm("{ .reg .u64 t; cvta.to.shared.u64 t, %1; cvt.u32.u64 %0, t; }"
        : "=r"(a) : "l"(p));
    return a;
}
__device__ __forceinline__ void cpa16(uint32_t dst, const void* src) {
    asm volatile("cp.async.cg.shared.global [%0], [%1], 16;"
                 :: "r"(dst), "l"(src));
}
__device__ __forceinline__ void cpa_commit() {
    asm volatile("cp.async.commit_group;" ::: "memory");
}
__device__ __forceinline__ void cpa_wait0() {
    asm volatile("cp.async.wait_group 0;" ::: "memory");
}
__device__ __forceinline__ void cpa_wait1() {
    asm volatile("cp.async.wait_group 1;" ::: "memory");
}
__device__ __forceinline__ void ldsm4(uint32_t* r, uint32_t addr) {
    asm volatile("ldmatrix.sync.aligned.m8n8.x4.shared.b16 {%0,%1,%2,%3}, [%4];"
                 : "=r"(r[0]), "=r"(r[1]), "=r"(r[2]), "=r"(r[3]) : "r"(addr));
}
__device__ __forceinline__ void ldsm4t(uint32_t* r, uint32_t addr) {
    asm volatile("ldmatrix.sync.aligned.m8n8.x4.trans.shared.b16 {%0,%1,%2,%3}, [%4];"
                 : "=r"(r[0]), "=r"(r[1]), "=r"(r[2]), "=r"(r[3]) : "r"(addr));
}
__device__ __forceinline__ void mma16816(float* c, const uint32_t* a,
                                         uint32_t b0, uint32_t b1) {
    asm volatile(
        "mma.sync.aligned.m16n8k16.row.col.f32.bf16.bf16.f32 "
        "{%0,%1,%2,%3}, {%4,%5,%6,%7}, {%8,%9}, {%0,%1,%2,%3};"
        : "+f"(c[0]), "+f"(c[1]), "+f"(c[2]), "+f"(c[3])
        : "r"(a[0]), "r"(a[1]), "r"(a[2]), "r"(a[3]), "r"(b0), "r"(b1));
}
__device__ __forceinline__ uint32_t bf2u(__nv_bfloat162 x) {
    uint32_t r; *(__nv_bfloat162*)&r = x; return r;
}
__device__ __forceinline__ void split_pack2(float a, float b,
                                            uint32_t& hi, uint32_t& lo) {
    __nv_bfloat162 h = __floats2bfloat162_rn(a, b);
    hi = bf2u(h);
    lo = bf2u(__floats2bfloat162_rn(a - __bfloat162float(h.x),
                                    b - __bfloat162float(h.y)));
}
// KV/Q tile: [rows][64bf16] 128B rows, SW128-style swizzle
__device__ __forceinline__ uint32_t swz(int row, int colB) {
    return (uint32_t)(((row << 7) + colB) ^ ((row & 7) << 4));
}
// sph/mask tile: [128 rows][32 w32] 128B rows, 16B-unit XOR swizzle
__device__ __forceinline__ uint32_t swzS(int row, int u) {
    return (uint32_t)((row << 7) + ((u ^ (row & 7)) << 4));
}

// ---------------- prep: fp32 K,V -> bf16 hi/lo scratch ----------------
__global__ __launch_bounds__(256)
void conv_kv(const float* __restrict__ k, const float* __restrict__ v)
{
    int idx = blockIdx.x * 256 + threadIdx.x;   // over NH*SQ*HD/4
    float4 kf = ((const float4*)k)[idx];
    uint32_t h0, l0, h1, l1;
    split_pack2(kf.x, kf.y, h0, l0);
    split_pack2(kf.z, kf.w, h1, l1);
    ((uint2*)g_khi)[idx] = make_uint2(h0, h1);
    ((uint2*)g_klo)[idx] = make_uint2(l0, l1);
    float4 vf = ((const float4*)v)[idx];
    split_pack2(vf.x, vf.y, h0, l0);
    split_pack2(vf.z, vf.w, h1, l1);
    ((uint2*)g_vhi)[idx] = make_uint2(h0, h1);
    ((uint2*)g_vlo)[idx] = make_uint2(l0, l1);
}

// ---------------- main fused attention (+ p normalization) ----------------
__global__ __launch_bounds__(THREADS)
void attn_mma(const float* __restrict__ q, const float* __restrict__ sph,
              const int* __restrict__ mask,
              float* __restrict__ out, float* __restrict__ p)
{
    extern __shared__ char smem[];
    const uint32_t sb = smem_u32(smem);
    float* osm  = (float*)(smem + S_OSM);
    float* l_sm = (float*)(smem + S_LSM);

    const int t = threadIdx.x, w = t >> 5, lane = t & 31;
    const int g = lane >> 2, lam = lane & 3;
    const int rt = w & 7;              // row-tile (16 rows)
    const int nh = w >> 3;             // kv-half of the 32-chunk
    const int h = blockIdx.y, q0 = blockIdx.x * MT;
    const int r0 = rt * 16 + g, r1 = r0 + 8;

    const float* qh  = q + ((size_t)h * SQ + q0) * HD;
    const float* sc0 = sph + ((size_t)h * SQ + q0) * SQ;
    const int*   mc0 = mask + ((size_t)h * SQ + q0) * SQ;
    float*       pc0 = p + ((size_t)h * SQ + q0) * SQ;
    __half*      ec0 = g_e + ((size_t)h * SQ + q0) * SQ;

    // ---- prologue: stage Q (x1/8) hi/lo, load A-frags into registers ----
    #pragma unroll
    for (int i = 0; i < 4; ++i) {                // 2048 float4 = 128x64
        int idx = t + THREADS * i;
        int row = idx >> 4, gq = idx & 15;
        float4 f = ((const float4*)qh)[idx];
        f.x *= 0.125f; f.y *= 0.125f; f.z *= 0.125f; f.w *= 0.125f;
        uint32_t h0, l0, h1, l1;
        split_pack2(f.x, f.y, h0, l0);
        split_pack2(f.z, f.w, h1, l1);
        uint32_t off = swz(row, gq * 8);
        *(uint2*)(smem + S_QHI + off) = make_uint2(h0, h1);
        *(uint2*)(smem + S_QLO + off) = make_uint2(l0, l1);
    }
    __syncthreads();
    uint32_t ah[4][4], al[4][4];
    {
        int arow = rt * 16 + ((lane >> 3) & 1) * 8 + (lane & 7);
        int acol = ((lane >> 4) & 1) * 16;
        #pragma unroll
        for (int kk = 0; kk < 4; ++kk) {
            uint32_t aoff = swz(arow, acol + kk * 32);
            ldsm4(ah[kk], sb + S_QHI + aoff);
            ldsm4(al[kk], sb + S_QLO + aoff);
        }
    }
    __syncthreads();   // Q overlay region becomes stage 0

    const __nv_bfloat16* kv0 = g_khi + (size_t)h * SQ * HD;
    const __nv_bfloat16* kv1 = g_klo + (size_t)h * SQ * HD;
    const __nv_bfloat16* kv2 = g_vhi + (size_t)h * SQ * HD;
    const __nv_bfloat16* kv3 = g_vlo + (size_t)h * SQ * HD;

    auto prefetch = [&](int cc, int st) {
        const uint32_t base = sb + (uint32_t)st * STG;
        #pragma unroll
        for (int it = 0; it < 2; ++it) {
            int idx = t + THREADS * it;     // 0..1023
            int arr = idx >> 8;
            int rem = idx & 255, row = rem >> 3, u = rem & 7;
            const __nv_bfloat16* src =
                (arr == 0 ? kv0 : arr == 1 ? kv1 : arr == 2 ? kv2 : kv3);
            cpa16(base + arr * 4096 + swz(row, u * 16),
                  src + (size_t)(cc + row) * HD + u * 8);
        }
        #pragma unroll
        for (int it = 0; it < 2; ++it) {
            int idx = t + THREADS * it;     // 0..1023 = 128 rows x 8 units
            int row = idx >> 3, u = idx & 7;
            uint32_t so = swzS(row, u);
            cpa16(base + 16384 + so, sc0 + (size_t)row * SQ + cc + u * 4);
            cpa16(base + 32768 + so, mc0 + (size_t)row * SQ + cc + u * 4);
        }
        cpa_commit();
    };

    prefetch(0, 0);
    prefetch(CH, 1);

    float O[8][4];
    #pragma unroll
    for (int a = 0; a < 8; ++a)
        #pragma unroll
        for (int b = 0; b < 4; ++b) O[a][b] = 0.f;
    float lacc0 = 0.f, lacc1 = 0.f;

    const uint32_t xr  = (uint32_t)(r0 & 7);           // sph/mask row xor key
    const int ksrow = (lane & 7);                      // K ldsm row-in-tile
    const int kssel = ((lane >> 3) & 1) * 16;
    const int kntad = (lane >> 4);                     // +0/+1 n-tile
    const int vrow  = (lane & 15);                     // V ldsm
    const int vntad = (lane >> 4);

    int st = 0;
    for (int ch = 0; ch < NCH; ++ch, st = (st == 2 ? 0 : st + 1)) {
        const int c0 = ch * CH;
        if (ch + 2 < NCH) cpa_wait1(); else cpa_wait0();
        __syncthreads();

        if (ch + 2 < NCH) {
            int st2 = st + 2; if (st2 >= 3) st2 -= 3;
            prefetch(c0 + 2 * CH, st2);
        }

        const uint32_t kvb = sb + (uint32_t)st * STG;

        // ---- QK^T for this warp's kv-half: S[2][4], 3 combos --------------
        float S[2][4];
        S[0][0] = S[0][1] = S[0][2] = S[0][3] = 0.f;
        S[1][0] = S[1][1] = S[1][2] = S[1][3] = 0.f;
        #pragma unroll
        for (int kk = 0; kk < 4; ++kk) {
            uint32_t koff = swz(nh * 16 + kntad * 8 + ksrow, kssel + kk * 32);
            uint32_t bh[4], bl[4];
            ldsm4(bh, kvb + koff);            // khi
            ldsm4(bl, kvb + 4096 + koff);     // klo
            mma16816(S[0], ah[kk], bh[0], bh[1]);
            mma16816(S[1], ah[kk], bh[2], bh[3]);
            mma16816(S[0], ah[kk], bl[0], bl[1]);
            mma16816(S[1], ah[kk], bl[2], bl[3]);
            mma16816(S[0], al[kk], bh[0], bh[1]);
            mma16816(S[1], al[kk], bh[2], bh[3]);
        }

        // ---- e = mask * exp(s*sph): f16 scratch stores, pack hi/lo --------
        uint32_t eh[4], el[4];
        const uint32_t sphb = kvb + 16384, mskb = kvb + 32768;
        #pragma unroll
        for (int nt = 0; nt < 2; ++nt) {
            uint32_t u = (uint32_t)(nh * 4 + 2 * nt + (lam >> 1));
            uint32_t off = ((u ^ xr) << 4) + ((lam & 1) << 3) + (r0 << 7);
            float2 sA = *(const float2*)(smem + (sphb - sb) + off);
            float2 sB = *(const float2*)(smem + (sphb - sb) + off + 1024);
            int2   mA = *(const int2*)(smem + (mskb - sb) + off);
            int2   mB = *(const int2*)(smem + (mskb - sb) + off + 1024);
            float e0 = mA.x ? __expf(S[nt][0] * sA.x) : 0.f;
            float e1 = mA.y ? __expf(S[nt][1] * sA.y) : 0.f;
            float e2 = mB.x ? __expf(S[nt][2] * sB.x) : 0.f;
            float e3 = mB.y ? __expf(S[nt][3] * sB.y) : 0.f;
            lacc0 += e0 + e1;
            lacc1 += e2 + e3;
            const int c = c0 + nh * 16 + nt * 8 + lam * 2;
            __half2 p0 = __float22half2_rn(make_float2(e0, e1));
            __half2 p1 = __float22half2_rn(make_float2(e2, e3));
            *(__half2*)(ec0 + (size_t)r0 * SQ + c) = p0;
            *(__half2*)(ec0 + (size_t)r1 * SQ + c) = p1;
            split_pack2(e0, e1, eh[nt * 2],     el[nt * 2]);
            split_pack2(e2, e3, eh[nt * 2 + 1], el[nt * 2 + 1]);
        }

        // ---- PV: O_partial += E * V(kv-half), 3 combos ---------------------
        #pragma unroll
        for (int ntp2 = 0; ntp2 < 4; ++ntp2) {
            uint32_t voff = swz(nh * 16 + vrow, (ntp2 * 2 + vntad) * 16);
            uint32_t bh[4], bl[4];
            ldsm4t(bh, kvb + 8192 + voff);    // vhi
            ldsm4t(bl, kvb + 12288 + voff);   // vlo
            mma16816(O[2 * ntp2],     eh, bh[0], bh[1]);
            mma16816(O[2 * ntp2 + 1], eh, bh[2], bh[3]);
            mma16816(O[2 * ntp2],     eh, bl[0], bl[1]);
            mma16816(O[2 * ntp2 + 1], eh, bl[2], bl[3]);
            mma16816(O[2 * ntp2],     el, bh[0], bh[1]);
            mma16816(O[2 * ntp2 + 1], el, bh[2], bh[3]);
        }
    }

    // ---- epilogue: reduce l and O across the two kv-half warp groups ------
    lacc0 += __shfl_xor_sync(0xffffffffu, lacc0, 1);
    lacc0 += __shfl_xor_sync(0xffffffffu, lacc0, 2);
    lacc1 += __shfl_xor_sync(0xffffffffu, lacc1, 1);
    lacc1 += __shfl_xor_sync(0xffffffffu, lacc1, 2);
    __syncthreads();   // all stage reads done; smem free for osm/l_sm
    if (lam == 0) {
        l_sm[nh * 128 + r0] = lacc0;
        l_sm[nh * 128 + r1] = lacc1;
    }
    if (nh == 1) {
        float* dst = osm + ((size_t)rt * 32 + lane) * 32;
        #pragma unroll
        for (int a = 0; a < 8; ++a)
            *(float4*)(dst + a * 4) =
                make_float4(O[a][0], O[a][1], O[a][2], O[a][3]);
    }
    __syncthreads();
    if (nh == 0) {
        const float* src = osm + ((size_t)rt * 32 + lane) * 32;
        #pragma unroll
        for (int a = 0; a < 8; ++a) {
            float4 x = *(const float4*)(src + a * 4);
            O[a][0] += x.x; O[a][1] += x.y; O[a][2] += x.z; O[a][3] += x.w;
        }
        const float inv0 = 1.0f / (l_sm[r0] + l_sm[128 + r0]);
        const float inv1 = 1.0f / (l_sm[r1] + l_sm[128 + r1]);
        float* o0 = out + ((size_t)h * SQ + q0 + r0) * HD;
        float* o1 = out + ((size_t)h * SQ + q0 + r1) * HD;
        #pragma unroll
        for (int nt2 = 0; nt2 < 8; ++nt2) {
            const int d = nt2 * 8 + lam * 2;
            *(float2*)(o0 + d) = make_float2(O[nt2][0] * inv0, O[nt2][1] * inv0);
            *(float2*)(o1 + d) = make_float2(O[nt2][2] * inv1, O[nt2][3] * inv1);
        }
    }

    // ---- fused p write: p = e/l from f16 scratch (L2-hot), 8 rows/warp ----
    #pragma unroll 1
    for (int rr = 0; rr < 8; ++rr) {
        const int row = w * 8 + rr;
        const float inv = 1.0f / (l_sm[row] + l_sm[128 + row]);
        const uint4* er = (const uint4*)(ec0 + (size_t)row * SQ);
        float4* pr = (float4*)(pc0 + (size_t)row * SQ);
        #pragma unroll
        for (int i = lane; i < SQ / 8; i += 32) {   // 256 uint4 per row
            uint4 x = __ldcg(er + i);
            float2 f0 = __half22float2(*(__half2*)&x.x);
            float2 f1 = __half22float2(*(__half2*)&x.y);
            float2 f2 = __half22float2(*(__half2*)&x.z);
            float2 f3 = __half22float2(*(__half2*)&x.w);
            __stcs(pr + 2 * i,
                   make_float4(f0.x * inv, f0.y * inv, f1.x * inv, f1.y * inv));
            __stcs(pr + 2 * i + 1,
                   make_float4(f2.x * inv, f2.y * inv, f3.x * inv, f3.y * inv));
        }
    }
}

extern "C" void kernel_launch(void* const* d_in, const int* in_sizes, int n_in,
                              void* d_out, int out_size)
{
    const float* q    = (const float*)d_in[0];
    const float* k    = (const float*)d_in[1];
    const float* v    = (const float*)d_in[2];
    const float* sph  = (const float*)d_in[3];
    const int*   mask = (const int*)d_in[4];

    float* out = (float*)d_out;                 // [1,8,2048,64]
    float* p   = out + (size_t)NH * SQ * HD;    // [1,8,2048,2048]

    cudaFuncSetAttribute(attn_mma, cudaFuncAttributeMaxDynamicSharedMemorySize,
                         S_TOTAL);

    conv_kv<<<NH * SQ * HD / 4 / 256, 256>>>(k, v);
    dim3 grid(SQ / MT, NH);
    attn_mma<<<grid, THREADS, S_TOTAL>>>(q, sph, mask, out, p);
}

// round 12
// speedup vs baseline: 1.5208x; 1.0828x over previous
#include <cuda_runtime.h>
#include <cuda_bf16.h>
#include <cuda_fp16.h>
#include <cstdint>

// ScaledDotProductAttention B=1 H=8 S=2048 D=64, sm_103 base ISA.
// R9 skeleton + LSU-diet: sph/mask loaded straight to registers (no smem),
// V single f16 (PV 1 combo), KV-only cp.async stages (12KB each).
// QK: bf16 hi/lo 3-combo. p written fp32 unnormalized in-loop; fused tail
// normalizes p via L2 re-read. d_out = [out | p_attn].

#define SQ 2048
#define HD 64
#define NH 8
#define MT 128          // q rows per CTA
#define CH 32           // kv per chunk
#define NCH (SQ / CH)   // 64
#define THREADS 512

// ---- smem layout (bytes) ----
// stage s at s*STG: khi 0 | klo 4096 | vh 8192   (12KB each, 3 stages)
#define STG   12288
#define S_QHI 36864                      // Q hi 16KB (prologue only)
#define S_QLO 53248                      // Q lo 16KB
#define S_TOTAL 69632
// epilogue overlays (stage area)
#define S_OSM 0                          // f32 [8][32][32] = 32KB
#define S_LSM 32768                      // f32 [2][128]

__device__ __nv_bfloat16 g_khi[NH * SQ * HD];
__device__ __nv_bfloat16 g_klo[NH * SQ * HD];
__device__ __half        g_vh [NH * SQ * HD];

__device__ __forceinline__ uint32_t smem_u32(const void* p) {
    uint32_t a;
    asm("{ .reg .u64 t; cvta.to.shared.u64 t, %1; cvt.u32.u64 %0, t; }"
        : "=r"(a) : "l"(p));
    return a;
}
__device__ __forceinline__ void cpa16(uint32_t dst, const void* src) {
    asm volatile("cp.async.cg.shared.global [%0], [%1], 16;"
                 :: "r"(dst), "l"(src));
}
__device__ __forceinline__ void cpa_commit() {
    asm volatile("cp.async.commit_group;" ::: "memory");
}
__device__ __forceinline__ void cpa_wait0() {
    asm volatile("cp.async.wait_group 0;" ::: "memory");
}
__device__ __forceinline__ void cpa_wait1() {
    asm volatile("cp.async.wait_group 1;" ::: "memory");
}
__device__ __forceinline__ void ldsm4(uint32_t* r, uint32_t addr) {
    asm volatile("ldmatrix.sync.aligned.m8n8.x4.shared.b16 {%0,%1,%2,%3}, [%4];"
                 : "=r"(r[0]), "=r"(r[1]), "=r"(r[2]), "=r"(r[3]) : "r"(addr));
}
__device__ __forceinline__ void ldsm4t(uint32_t* r, uint32_t addr) {
    asm volatile("ldmatrix.sync.aligned.m8n8.x4.trans.shared.b16 {%0,%1,%2,%3}, [%4];"
                 : "=r"(r[0]), "=r"(r[1]), "=r"(r[2]), "=r"(r[3]) : "r"(addr));
}
__device__ __forceinline__ void mma_bf16(float* c, const uint32_t* a,
                                         uint32_t b0, uint32_t b1) {
    asm volatile(
        "mma.sync.aligned.m16n8k16.row.col.f32.bf16.bf16.f32 "
        "{%0,%1,%2,%3}, {%4,%5,%6,%7}, {%8,%9}, {%0,%1,%2,%3};"
        : "+f"(c[0]), "+f"(c[1]), "+f"(c[2]), "+f"(c[3])
        : "r"(a[0]), "r"(a[1]), "r"(a[2]), "r"(a[3]), "r"(b0), "r"(b1));
}
__device__ __forceinline__ void mma_f16(float* c, const uint32_t* a,
                                        uint32_t b0, uint32_t b1) {
    asm volatile(
        "mma.sync.aligned.m16n8k16.row.col.f32.f16.f16.f32 "
        "{%0,%1,%2,%3}, {%4,%5,%6,%7}, {%8,%9}, {%0,%1,%2,%3};"
        : "+f"(c[0]), "+f"(c[1]), "+f"(c[2]), "+f"(c[3])
        : "r"(a[0]), "r"(a[1]), "r"(a[2]), "r"(a[3]), "r"(b0), "r"(b1));
}
__device__ __forceinline__ uint32_t bf2u(__nv_bfloat162 x) {
    uint32_t r; *(__nv_bfloat162*)&r = x; return r;
}
__device__ __forceinline__ void split_pack2(float a, float b,
                                            uint32_t& hi, uint32_t& lo) {
    __nv_bfloat162 h = __floats2bfloat162_rn(a, b);
    hi = bf2u(h);
    lo = bf2u(__floats2bfloat162_rn(a - __bfloat162float(h.x),
                                    b - __bfloat162float(h.y)));
}
__device__ __forceinline__ uint32_t h2u(__half2 x) {
    uint32_t r; *(__half2*)&r = x; return r;
}
// 128B-row tiles: SW128-style swizzle
__device__ __forceinline__ uint32_t swz(int row, int colB) {
    return (uint32_t)(((row << 7) + colB) ^ ((row & 7) << 4));
}

// ---------------- prep: K -> bf16 hi/lo, V -> f16 ----------------
__global__ __launch_bounds__(256)
void conv_kv(const float* __restrict__ k, const float* __restrict__ v)
{
    int idx = blockIdx.x * 256 + threadIdx.x;   // over NH*SQ*HD/4
    float4 kf = ((const float4*)k)[idx];
    uint32_t h0, l0, h1, l1;
    split_pack2(kf.x, kf.y, h0, l0);
    split_pack2(kf.z, kf.w, h1, l1);
    ((uint2*)g_khi)[idx] = make_uint2(h0, h1);
    ((uint2*)g_klo)[idx] = make_uint2(l0, l1);
    float4 vf = ((const float4*)v)[idx];
    __half2 v0 = __float22half2_rn(make_float2(vf.x, vf.y));
    __half2 v1 = __float22half2_rn(make_float2(vf.z, vf.w));
    ((uint2*)g_vh)[idx] = make_uint2(h2u(v0), h2u(v1));
}

// ---------------- main fused attention (+ p normalization) ----------------
__global__ __launch_bounds__(THREADS)
void attn_mma(const float* __restrict__ q, const float* __restrict__ sph,
              const int* __restrict__ mask,
              float* __restrict__ out, float* __restrict__ p)
{
    extern __shared__ char smem[];
    const uint32_t sb = smem_u32(smem);
    float* osm  = (float*)(smem + S_OSM);
    float* l_sm = (float*)(smem + S_LSM);

    const int t = threadIdx.x, w = t >> 5, lane = t & 31;
    const int g = lane >> 2, lam = lane & 3;
    const int rt = w & 7;              // row-tile (16 rows)
    const int nh = w >> 3;             // kv-half of the 32-chunk
    const int h = blockIdx.y, q0 = blockIdx.x * MT;
    const int r0 = rt * 16 + g, r1 = r0 + 8;

    const float* qh  = q + ((size_t)h * SQ + q0) * HD;
    const float* sc0 = sph + ((size_t)h * SQ + q0) * SQ;
    const int*   mc0 = mask + ((size_t)h * SQ + q0) * SQ;
    float*       pc0 = p + ((size_t)h * SQ + q0) * SQ;

    const __nv_bfloat16* kh = g_khi + (size_t)h * SQ * HD;
    const __nv_bfloat16* kl = g_klo + (size_t)h * SQ * HD;
    const __half*        vv = g_vh  + (size_t)h * SQ * HD;

    // KV-only stage prefetch: 768 16B units (khi 256 | klo 256 | vh 256)
    auto prefetch = [&](int cc, int st) {
        const uint32_t base = sb + (uint32_t)st * STG;
        #pragma unroll
        for (int it = 0; it < 2; ++it) {
            int idx = t + THREADS * it;
            if (idx < 768) {
                int arr = idx >> 8;
                int rem = idx & 255, row = rem >> 3, u = rem & 7;
                const void* src = (arr == 0)
                    ? (const void*)(kh + (size_t)(cc + row) * HD + u * 8)
                    : (arr == 1)
                    ? (const void*)(kl + (size_t)(cc + row) * HD + u * 8)
                    : (const void*)(vv + (size_t)(cc + row) * HD + u * 8);
                cpa16(base + arr * 4096 + swz(row, u * 16), src);
            }
        }
        cpa_commit();
    };

    prefetch(0, 0);
    prefetch(CH, 1);

    // ---- prologue: stage Q (x1/8) hi/lo, load A-frags into registers ----
    #pragma unroll
    for (int i = 0; i < 4; ++i) {                // 2048 float4 = 128x64
        int idx = t + THREADS * i;
        int row = idx >> 4, gq = idx & 15;
        float4 f = ((const float4*)qh)[idx];
        f.x *= 0.125f; f.y *= 0.125f; f.z *= 0.125f; f.w *= 0.125f;
        uint32_t h0, l0, h1, l1;
        split_pack2(f.x, f.y, h0, l0);
        split_pack2(f.z, f.w, h1, l1);
        uint32_t off = swz(row, gq * 8);
        *(uint2*)(smem + S_QHI + off) = make_uint2(h0, h1);
        *(uint2*)(smem + S_QLO + off) = make_uint2(l0, l1);
    }
    __syncthreads();
    uint32_t ah[4][4], al[4][4];
    {
        int arow = rt * 16 + ((lane >> 3) & 1) * 8 + (lane & 7);
        int acol = ((lane >> 4) & 1) * 16;
        #pragma unroll
        for (int kk = 0; kk < 4; ++kk) {
            uint32_t aoff = swz(arow, acol + kk * 32);
            ldsm4(ah[kk], sb + S_QHI + aoff);
            ldsm4(al[kk], sb + S_QLO + aoff);
        }
    }

    float O[8][4];
    #pragma unroll
    for (int a = 0; a < 8; ++a)
        #pragma unroll
        for (int b = 0; b < 4; ++b) O[a][b] = 0.f;
    float lacc0 = 0.f, lacc1 = 0.f;

    const int ksrow = (lane & 7);                      // K ldsm row-in-tile
    const int kssel = ((lane >> 3) & 1) * 16;
    const int kntad = (lane >> 4);                     // +0/+1 n-tile
    const int vrow  = (lane & 15);                     // V ldsm
    const int vntad = (lane >> 4);
    const int cbase = nh * 16 + lam * 2;               // this thread's col base

    int st = 0;
    for (int ch = 0; ch < NCH; ++ch, st = (st == 2 ? 0 : st + 1)) {
        const int c0 = ch * CH;

        // ---- sph/mask straight to registers (overlaps wait + QK) ----------
        float2 spr[2][2]; int2 mkr[2][2];
        #pragma unroll
        for (int nt = 0; nt < 2; ++nt)
            #pragma unroll
            for (int hf = 0; hf < 2; ++hf) {
                const size_t off = (size_t)(rt * 16 + hf * 8 + g) * SQ
                                 + c0 + cbase + nt * 8;
                spr[nt][hf] = __ldcs((const float2*)(sc0 + off));
                mkr[nt][hf] = __ldcs((const int2*)(mc0 + off));
            }

        if (ch + 2 < NCH) cpa_wait1(); else cpa_wait0();
        __syncthreads();

        if (ch + 2 < NCH) {
            int st2 = st + 2; if (st2 >= 3) st2 -= 3;
            prefetch(c0 + 2 * CH, st2);
        }

        const uint32_t kvb = sb + (uint32_t)st * STG;

        // ---- QK^T for this warp's kv-half: S[2][4], 3 combos --------------
        float S[2][4];
        S[0][0] = S[0][1] = S[0][2] = S[0][3] = 0.f;
        S[1][0] = S[1][1] = S[1][2] = S[1][3] = 0.f;
        #pragma unroll
        for (int kk = 0; kk < 4; ++kk) {
            uint32_t koff = swz(nh * 16 + kntad * 8 + ksrow, kssel + kk * 32);
            uint32_t bh[4], bl[4];
            ldsm4(bh, kvb + koff);            // khi
            ldsm4(bl, kvb + 4096 + koff);     // klo
            mma_bf16(S[0], ah[kk], bh[0], bh[1]);
            mma_bf16(S[1], ah[kk], bh[2], bh[3]);
            mma_bf16(S[0], ah[kk], bl[0], bl[1]);
            mma_bf16(S[1], ah[kk], bl[2], bl[3]);
            mma_bf16(S[0], al[kk], bh[0], bh[1]);
            mma_bf16(S[1], al[kk], bh[2], bh[3]);
        }

        // ---- e = mask * exp(s*sph): p fp32 stores, pack e -> f16 frags -----
        uint32_t ea[4];
        #pragma unroll
        for (int nt = 0; nt < 2; ++nt) {
            float e0 = mkr[nt][0].x ? __expf(S[nt][0] * spr[nt][0].x) : 0.f;
            float e1 = mkr[nt][0].y ? __expf(S[nt][1] * spr[nt][0].y) : 0.f;
            float e2 = mkr[nt][1].x ? __expf(S[nt][2] * spr[nt][1].x) : 0.f;
            float e3 = mkr[nt][1].y ? __expf(S[nt][3] * spr[nt][1].y) : 0.f;
            lacc0 += e0 + e1;
            lacc1 += e2 + e3;
            const int c = c0 + cbase + nt * 8;
            *(float2*)(pc0 + (size_t)r0 * SQ + c) = make_float2(e0, e1);
            *(float2*)(pc0 + (size_t)r1 * SQ + c) = make_float2(e2, e3);
            ea[nt * 2]     = h2u(__float22half2_rn(make_float2(e0, e1)));
            ea[nt * 2 + 1] = h2u(__float22half2_rn(make_float2(e2, e3)));
        }

        // ---- PV: O_partial += E(f16) * V(f16), single combo ----------------
        #pragma unroll
        for (int ntp2 = 0; ntp2 < 4; ++ntp2) {
            uint32_t voff = swz(nh * 16 + vrow, (ntp2 * 2 + vntad) * 16);
            uint32_t vb[4];
            ldsm4t(vb, kvb + 8192 + voff);
            mma_f16(O[2 * ntp2],     ea, vb[0], vb[1]);
            mma_f16(O[2 * ntp2 + 1], ea, vb[2], vb[3]);
        }
    }

    // ---- epilogue: reduce l and O across the two kv-half warp groups ------
    lacc0 += __shfl_xor_sync(0xffffffffu, lacc0, 1);
    lacc0 += __shfl_xor_sync(0xffffffffu, lacc0, 2);
    lacc1 += __shfl_xor_sync(0xffffffffu, lacc1, 1);
    lacc1 += __shfl_xor_sync(0xffffffffu, lacc1, 2);
    __syncthreads();   // all stage reads done; smem free for osm/l_sm
    if (lam == 0) {
        l_sm[nh * 128 + r0] = lacc0;
        l_sm[nh * 128 + r1] = lacc1;
    }
    if (nh == 1) {
        float* dst = osm + ((size_t)rt * 32 + lane) * 32;
        #pragma unroll
        for (int a = 0; a < 8; ++a)
            *(float4*)(dst + a * 4) =
                make_float4(O[a][0], O[a][1], O[a][2], O[a][3]);
    }
    __syncthreads();
    if (nh == 0) {
        const float* src = osm + ((size_t)rt * 32 + lane) * 32;
        #pragma unroll
        for (int a = 0; a < 8; ++a) {
            float4 x = *(const float4*)(src + a * 4);
            O[a][0] += x.x; O[a][1] += x.y; O[a][2] += x.z; O[a][3] += x.w;
        }
        const float inv0 = 1.0f / (l_sm[r0] + l_sm[128 + r0]);
        const float inv1 = 1.0f / (l_sm[r1] + l_sm[128 + r1]);
        float* o0 = out + ((size_t)h * SQ + q0 + r0) * HD;
        float* o1 = out + ((size_t)h * SQ + q0 + r1) * HD;
        #pragma unroll
        for (int nt2 = 0; nt2 < 8; ++nt2) {
            const int d = nt2 * 8 + lam * 2;
            *(float2*)(o0 + d) = make_float2(O[nt2][0] * inv0, O[nt2][1] * inv0);
            *(float2*)(o1 + d) = make_float2(O[nt2][2] * inv1, O[nt2][3] * inv1);
        }
    }

    // ---- fused p normalization: each warp rescales its 8 rows (L2-hot) ----
    #pragma unroll 1
    for (int rr = 0; rr < 8; ++rr) {
        const int row = w * 8 + rr;
        const float inv = 1.0f / (l_sm[row] + l_sm[128 + row]);
        float4* pr = (float4*)(pc0 + (size_t)row * SQ);
        #pragma unroll
        for (int i = lane; i < SQ / 4; i += 32) {
            float4 x = __ldcg((const float4*)(pr + i));
            x.x *= inv; x.y *= inv; x.z *= inv; x.w *= inv;
            __stcs((float4*)(pr + i), x);
        }
    }
}

extern "C" void kernel_launch(void* const* d_in, const int* in_sizes, int n_in,
                              void* d_out, int out_size)
{
    const float* q    = (const float*)d_in[0];
    const float* k    = (const float*)d_in[1];
    const float* v    = (const float*)d_in[2];
    const float* sph  = (const float*)d_in[3];
    const int*   mask = (const int*)d_in[4];

    float* out = (float*)d_out;                 // [1,8,2048,64]
    float* p   = out + (size_t)NH * SQ * HD;    // [1,8,2048,2048]

    cudaFuncSetAttribute(attn_mma, cudaFuncAttributeMaxDynamicSharedMemorySize,
                         S_TOTAL);

    conv_kv<<<NH * SQ * HD / 4 / 256, 256>>>(k, v);
    dim3 grid(SQ / MT, NH);
    attn_mma<<<grid, THREADS, S_TOTAL>>>(q, sph, mask, out, p);
}